// round 8
// baseline (speedup 1.0000x reference)
#include <cuda_runtime.h>
#include <math.h>

#define B 8
#define S 1024
#define INDIM 512
#define H 512
#define NH 8
#define HD 64
#define BS (B*S)

// ---------------- scratch (static __device__; no allocations) ----------------
__device__ float g_h[BS*H];
__device__ float g_qkv[BS*3*H];
__device__ float g_ctx[BS*H];
__device__ float g_tmp[BS*H];
__device__ float g_hatt[BS*H];
__device__ float g_prex[BS*H];
__device__ float g_outs[BS*H];
__device__ float g_W2T[H*H];
__device__ float g_Wc[3*H*H];
__device__ float g_bc[3*H];
__device__ float g_z[B*H];
__device__ __align__(128) unsigned g_barctr4[128];   // group g -> [g*32]

__global__ void init_kernel() {
    if (threadIdx.x < 128) g_barctr4[threadIdx.x] = 0u;
}

// ---------------- f32x2 packed helpers (scan only) ----------------
__device__ __forceinline__ void ffma2(unsigned long long &d, unsigned long long a, unsigned long long b) {
    asm("fma.rn.f32x2 %0, %1, %2, %0;" : "+l"(d) : "l"(a), "l"(b));
}
__device__ __forceinline__ void unpack2(unsigned long long v, float &x, float &y) {
    unsigned lo, hi; asm("mov.b64 {%0, %1}, %2;" : "=r"(lo), "=r"(hi) : "l"(v));
    x = __uint_as_float(lo); y = __uint_as_float(hi);
}
__device__ __forceinline__ float hsum2(unsigned long long v) {
    float x, y; unpack2(v, x, y); return x + y;
}
__device__ __forceinline__ void ldcg2(const float* p, unsigned long long &x, unsigned long long &y) {
    asm volatile("ld.global.cg.v2.u64 {%0, %1}, [%2];" : "=l"(x), "=l"(y) : "l"(p));
}

// ---------------- generic fp32 GEMM: C[M,N] = A[M,K] * W[N,K]^T + bias ----------------
__global__ __launch_bounds__(256) void gemm_tn(
    const float* __restrict__ A, int lda,
    const float* __restrict__ W, int ldw,
    const float* __restrict__ bias,
    float* __restrict__ C,
    int M, int N, int K)
{
    __shared__ float As[16][64];
    __shared__ float Ws[16][64];
    int tid = threadIdx.x;
    int tx = tid & 15, ty = tid >> 4;
    int bm = blockIdx.y * 64, bn = blockIdx.x * 64;
    int lr = tid >> 2;
    int lk = (tid & 3) << 2;
    const float* Ap = A + (size_t)(bm + lr) * lda + lk;
    const float* Wp = W + (size_t)(bn + lr) * ldw + lk;
    float acc[4][4];
#pragma unroll
    for (int i = 0; i < 4; i++)
#pragma unroll
        for (int j = 0; j < 4; j++) acc[i][j] = 0.f;

    for (int k0 = 0; k0 < K; k0 += 16) {
        float4 av = *(const float4*)(Ap + k0);
        float4 wv = *(const float4*)(Wp + k0);
        __syncthreads();
        As[lk + 0][lr] = av.x; As[lk + 1][lr] = av.y; As[lk + 2][lr] = av.z; As[lk + 3][lr] = av.w;
        Ws[lk + 0][lr] = wv.x; Ws[lk + 1][lr] = wv.y; Ws[lk + 2][lr] = wv.z; Ws[lk + 3][lr] = wv.w;
        __syncthreads();
#pragma unroll
        for (int kk = 0; kk < 16; kk++) {
            float4 a = *(const float4*)&As[kk][ty << 2];
            float4 w = *(const float4*)&Ws[kk][tx << 2];
            float ar[4] = {a.x, a.y, a.z, a.w};
            float wr[4] = {w.x, w.y, w.z, w.w};
#pragma unroll
            for (int i = 0; i < 4; i++)
#pragma unroll
                for (int j = 0; j < 4; j++)
                    acc[i][j] += ar[i] * wr[j];
        }
    }
#pragma unroll
    for (int j = 0; j < 4; j++) {
        int n = bn + (tx << 2) + j;
        float bv = bias ? bias[n] : 0.f;
#pragma unroll
        for (int i = 0; i < 4; i++) {
            int m = bm + (ty << 2) + i;
            C[(size_t)m * N + n] = acc[i][j] + bv;
        }
    }
}

// ---------------- flash attention (fp32, no mask), 32-key tiles ----------------
__global__ __launch_bounds__(128) void attn_kernel(const float* __restrict__ qkv,
                                                   float* __restrict__ ctx)
{
    __shared__ float Ks[32][64];
    __shared__ float Vs[32][64];
    int qt = blockIdx.x;          // q tile (16)
    int bh = blockIdx.y;          // b*NH+h (64)
    int b = bh >> 3, h = bh & 7;
    const float* base = qkv + (size_t)b * S * 1536;
    int tid = threadIdx.x;
    int r = tid >> 1, half = tid & 1;   // 2 threads per q-row, split over HD
    int qrow = qt * 64 + r;

    float q[32];
    {
        const float* qp = base + (size_t)qrow * 1536 + h * 64 + half * 32;
#pragma unroll
        for (int i = 0; i < 32; i++) q[i] = qp[i] * 0.125f;   // 1/sqrt(64)
    }
    float m = -1e30f, l = 0.f;
    float acc[32];
#pragma unroll
    for (int i = 0; i < 32; i++) acc[i] = 0.f;

    for (int kt = 0; kt < 32; kt++) {
        __syncthreads();
#pragma unroll
        for (int ii = 0; ii < 4; ii++) {
            int fi = tid + 128 * ii;          // 0..511 float4s
            int row = fi >> 4;
            int d4 = (fi & 15) << 2;
            const float* kp = base + (size_t)(kt * 32 + row) * 1536 + 512 + h * 64 + d4;
            *(float4*)&Ks[row][d4] = *(const float4*)kp;
            *(float4*)&Vs[row][d4] = *(const float4*)(kp + 512);
        }
        __syncthreads();

        float s[32];
#pragma unroll
        for (int j = 0; j < 32; j++) {
            float a = 0.f;
#pragma unroll
            for (int i = 0; i < 32; i += 4) {
                float4 kk = *(const float4*)&Ks[j][half * 32 + i];
                a += q[i] * kk.x + q[i + 1] * kk.y + q[i + 2] * kk.z + q[i + 3] * kk.w;
            }
            s[j] = a;
        }
#pragma unroll
        for (int j = 0; j < 32; j++) s[j] += __shfl_xor_sync(0xffffffffu, s[j], 1);

        float mx = s[0];
#pragma unroll
        for (int j = 1; j < 32; j++) mx = fmaxf(mx, s[j]);
        float mnew = fmaxf(m, mx);
        float corr = __expf(m - mnew);
        l *= corr;
#pragma unroll
        for (int i = 0; i < 32; i++) acc[i] *= corr;
        float ls = 0.f;
#pragma unroll
        for (int j = 0; j < 32; j++) { float p = __expf(s[j] - mnew); s[j] = p; ls += p; }
        l += ls;
        m = mnew;
#pragma unroll
        for (int j = 0; j < 32; j++) {
#pragma unroll
            for (int i = 0; i < 32; i += 4) {
                float4 vv = *(const float4*)&Vs[j][half * 32 + i];
                acc[i]     += s[j] * vv.x;
                acc[i + 1] += s[j] * vv.y;
                acc[i + 2] += s[j] * vv.z;
                acc[i + 3] += s[j] * vv.w;
            }
        }
    }
    float inv = 1.f / l;
    float* op = ctx + ((size_t)b * S + qrow) * 512 + h * 64 + half * 32;
#pragma unroll
    for (int i = 0; i < 32; i++) op[i] = acc[i] * inv;
}

// ---------------- fused residual + LayerNorm ----------------
__global__ __launch_bounds__(128) void ln_kernel(
    const float* __restrict__ A, const float* __restrict__ Bres,
    const float* __restrict__ gma, const float* __restrict__ bta,
    float* __restrict__ out)
{
    int row = blockIdx.x, tid = threadIdx.x;
    const float4* a4 = (const float4*)(A + (size_t)row * 512);
    const float4* b4 = (const float4*)(Bres + (size_t)row * 512);
    float4 x = a4[tid], y = b4[tid];
    float4 v = make_float4(x.x + y.x, x.y + y.y, x.z + y.z, x.w + y.w);
    float s = v.x + v.y + v.z + v.w;
    float q = v.x * v.x + v.y * v.y + v.z * v.z + v.w * v.w;
#pragma unroll
    for (int o = 16; o > 0; o >>= 1) {
        s += __shfl_down_sync(0xffffffffu, s, o);
        q += __shfl_down_sync(0xffffffffu, q, o);
    }
    __shared__ float rs[4], rq[4];
    int wid = tid >> 5;
    if ((tid & 31) == 0) { rs[wid] = s; rq[wid] = q; }
    __syncthreads();
    float ts = rs[0] + rs[1] + rs[2] + rs[3];
    float tq = rq[0] + rq[1] + rq[2] + rq[3];
    float mean = ts * (1.f / 512.f);
    float var = tq * (1.f / 512.f) - mean * mean;
    float rstd = rsqrtf(var + 1e-5f);
    float4 gg = ((const float4*)gma)[tid];
    float4 bb = ((const float4*)bta)[tid];
    float4 o;
    o.x = (v.x - mean) * rstd * gg.x + bb.x;
    o.y = (v.y - mean) * rstd * gg.y + bb.y;
    o.z = (v.z - mean) * rstd * gg.z + bb.z;
    o.w = (v.w - mean) * rstd * gg.w + bb.w;
    ((float4*)(out + (size_t)row * 512))[tid] = o;
}

// ---------------- 512x512 transpose ----------------
__global__ void transpose_kernel(const float* __restrict__ in, float* __restrict__ out)
{
    __shared__ float tile[32][33];
    int bx = blockIdx.x * 32, by = blockIdx.y * 32;
    int tx = threadIdx.x, ty = threadIdx.y;  // (32, 8)
    for (int i = 0; i < 32; i += 8)
        tile[ty + i][tx] = in[(size_t)(by + ty + i) * 512 + bx + tx];
    __syncthreads();
    for (int i = 0; i < 32; i += 8)
        out[(size_t)(bx + ty + i) * 512 + by + tx] = tile[tx][ty + i];
}

// ---------------- bc = Wfgh @ b2 + b_fgh ----------------
__global__ void bc_kernel(const float* __restrict__ tw, const float* __restrict__ gw,
                          const float* __restrict__ hw, const float* __restrict__ tb,
                          const float* __restrict__ gb, const float* __restrict__ hb,
                          const float* __restrict__ b2)
{
    int i = blockIdx.x * blockDim.x + threadIdx.x;
    if (i >= 1536) return;
    int part = i >> 9, r = i & 511;
    const float* Wr; float bv;
    if (part == 0)      { Wr = tw + (size_t)r * 512; bv = tb[r]; }
    else if (part == 1) { Wr = gw + (size_t)r * 512; bv = gb[r]; }
    else                { Wr = hw + (size_t)r * 512; bv = hb[r]; }
    float s = bv;
    for (int j = 0; j < 512; j++) s += Wr[j] * b2[j];
    g_bc[i] = s;
}

// ---------------- persistent LTC scan ----------------
// 128 CTAs in 4 INDEPENDENT groups of 32 (2 batches per group; batches are
// independent recurrences). Each group has its own counter line, so each
// barrier serializes only 32 arrivals. Mechanism: R2/R7-proven red.release
// arrival + single acquire-load self-poll.
#define NBLK 128
#define GRP_CTAS 32
#define SCAN_SMEM (64 * 512 * 4)   // sW1 16 rows + sWc 48 rows, fp32

__device__ __forceinline__ void gridbar_grp(unsigned* ctr, unsigned target)
{
    __syncthreads();
    if (threadIdx.x == 0) {
        asm volatile("red.release.gpu.global.add.u32 [%0], %1;" :: "l"(ctr), "r"(1u) : "memory");
        unsigned v;
        do {
            asm volatile("ld.acquire.gpu.global.u32 %0, [%1];" : "=r"(v) : "l"(ctr) : "memory");
        } while (v < target);
    }
    __syncthreads();
}

// CTA owns 16 columns (c0..c0+15) of its group's 2 batches (b0, b0+1).
// Warp w (0..3): stage1 rows c0+4w..c0+4w+3; stage2 rows part*16+4w+r
// (part = f/g/h). Lane owns k in { lane*4 + 128*i : i=0..3 } -> each LDS.128/
// LDG.128 is a contiguous 512B warp-block (conflict-free, coalesced). Each
// weight float4 read serves 2 batches; activations serve 4/12 rows.
__global__ __launch_bounds__(128) void scan_kernel(const float* __restrict__ ltc_w1)
{
    extern __shared__ float dsm[];
    float* sW1 = dsm;              // [16][512]
    float* sWc = dsm + 16 * 512;   // [48][512]: f rows 0-15, g 16-31, h 32-47
    __shared__ float sbc[48];
    int blk = blockIdx.x, tid = threadIdx.x;
    int grp = blk >> 5;            // 0..3
    int cblk = blk & 31;
    int c0 = cblk * 16;
    int b0 = grp * 2;
    unsigned* ctr = &g_barctr4[grp * 32];

#pragma unroll
    for (int r = 0; r < 16; r++)
        for (int k = tid; k < 512; k += 128)
            sW1[r * 512 + k] = ltc_w1[(size_t)(c0 + r) * 1024 + 512 + k];
#pragma unroll
    for (int r = 0; r < 48; r++) {
        int row = (r >> 4) * 512 + c0 + (r & 15);
        for (int k = tid; k < 512; k += 128)
            sWc[r * 512 + k] = g_Wc[(size_t)row * 512 + k];
    }
    if (tid < 48) sbc[tid] = g_bc[(tid >> 4) * 512 + c0 + (tid & 15)];
    __syncthreads();

    int w = tid >> 5, lane = tid & 31;
    int wcs = lane & 3;              // writer col-sub (lanes 0-7)
    int wb = b0 + (lane >> 2);       // writer batch (lanes 0-7)
    int wcol = c0 + 4 * w + wcs;     // writer global column
    unsigned ph = 0;

    for (int t = 0; t < S; t++) {
        // hoisted prex load (barrier-independent)
        float prexv = 0.f;
        if (lane < 8)
            prexv = g_prex[((size_t)wb * S + t) * H + wcol];

        // ---- stage 1: z = tanh(prex + state @ W1h^T), 4 rows x 2 batches ----
        float s1 = 0.f;
        {
            unsigned long long acc[8];
#pragma unroll
            for (int r = 0; r < 8; r++) acc[r] = 0ull;
            if (t > 0) {
                const float* st0 = g_outs + ((size_t)b0 * S + (t - 1)) * H;
                const float* st1 = g_outs + ((size_t)(b0 + 1) * S + (t - 1)) * H;
#pragma unroll
                for (int i = 0; i < 4; i++) {
                    int k = lane * 4 + 128 * i;
                    unsigned long long sx0, sy0, sx1, sy1;
                    ldcg2(st0 + k, sx0, sy0);
                    ldcg2(st1 + k, sx1, sy1);
#pragma unroll
                    for (int r = 0; r < 4; r++) {
                        ulonglong2 wv = *(const ulonglong2*)&sW1[(4 * w + r) * 512 + k];
                        ffma2(acc[2 * r + 0], sx0, wv.x); ffma2(acc[2 * r + 0], sy0, wv.y);
                        ffma2(acc[2 * r + 1], sx1, wv.x); ffma2(acc[2 * r + 1], sy1, wv.y);
                    }
                }
            }
#pragma unroll
            for (int r = 0; r < 8; r++) {
                float a = hsum2(acc[r]);
#pragma unroll
                for (int o = 1; o <= 16; o <<= 1)
                    a += __shfl_xor_sync(0xffffffffu, a, o);
                if (r == 2 * wcs + (lane >> 2)) s1 = a;   // writer picks its (col,batch)
            }
        }
        if (lane < 8) {
            float z = tanhf(prexv + s1);
            g_z[wb * H + wcol] = z;
        }
        gridbar_grp(ctr, (++ph) * GRP_CTAS);

        // ---- stage 2: fgh = z @ Wc^T + bc; state update. 12 rows x 2 batches ----
        float s2[24];
        {
            unsigned long long acc[24];
#pragma unroll
            for (int r = 0; r < 24; r++) acc[r] = 0ull;
            const float* z0 = g_z + b0 * H;
            const float* z1 = g_z + (b0 + 1) * H;
#pragma unroll
            for (int i = 0; i < 4; i++) {
                int k = lane * 4 + 128 * i;
                unsigned long long zx0, zy0, zx1, zy1;
                ldcg2(z0 + k, zx0, zy0);
                ldcg2(z1 + k, zx1, zy1);
#pragma unroll
                for (int r = 0; r < 12; r++) {
                    int lrow = (r >> 2) * 16 + 4 * w + (r & 3);
                    ulonglong2 wv = *(const ulonglong2*)&sWc[lrow * 512 + k];
                    ffma2(acc[2 * r + 0], zx0, wv.x); ffma2(acc[2 * r + 0], zy0, wv.y);
                    ffma2(acc[2 * r + 1], zx1, wv.x); ffma2(acc[2 * r + 1], zy1, wv.y);
                }
            }
#pragma unroll
            for (int r = 0; r < 24; r++) {
                float a = hsum2(acc[r]);
#pragma unroll
                for (int o = 1; o <= 16; o <<= 1)
                    a += __shfl_xor_sync(0xffffffffu, a, o);
                s2[r] = a;
            }
        }
        if (lane < 8) {
            int bsel = lane >> 2;
            float fv = s2[2 * (0 + wcs) + bsel] + sbc[0  + 4 * w + wcs];
            float gv = s2[2 * (4 + wcs) + bsel] + sbc[16 + 4 * w + wcs];
            float hv = s2[2 * (8 + wcs) + bsel] + sbc[32 + 4 * w + wcs];
            float ftv = 1.f / (1.f + __expf(-fv));              // sigmoid(f)
            float gate = 1.f / (1.f + __expf(ftv * (float)t));  // sigmoid(-ft * t)
            float sv = gate * gv + (1.f - gate) * hv;
            g_outs[((size_t)wb * S + t) * H + wcol] = sv;
        }
        gridbar_grp(ctr, (++ph) * GRP_CTAS);
    }
}

// ---------------- host launch ----------------
extern "C" void kernel_launch(void* const* d_in, const int* in_sizes, int n_in,
                              void* d_out, int out_size)
{
    const float* x    = (const float*)d_in[0];
    const float* ipw  = (const float*)d_in[1];
    const float* ipb  = (const float*)d_in[2];
    const float* qkvw = (const float*)d_in[3];
    const float* qkvb = (const float*)d_in[4];
    const float* aow  = (const float*)d_in[5];
    const float* aob  = (const float*)d_in[6];
    const float* w1   = (const float*)d_in[7];
    const float* b1   = (const float*)d_in[8];
    const float* w2   = (const float*)d_in[9];
    const float* b2   = (const float*)d_in[10];
    const float* tw   = (const float*)d_in[11];
    const float* tb   = (const float*)d_in[12];
    const float* gw   = (const float*)d_in[13];
    const float* gb   = (const float*)d_in[14];
    const float* hw   = (const float*)d_in[15];
    const float* hb   = (const float*)d_in[16];
    const float* n1g  = (const float*)d_in[17];
    const float* n1b  = (const float*)d_in[18];
    const float* n2g  = (const float*)d_in[19];
    const float* n2b  = (const float*)d_in[20];
    const float* ow   = (const float*)d_in[21];
    const float* ob   = (const float*)d_in[22];
    float* out = (float*)d_out;

    float *ph, *pqkv, *pctx, *ptmp, *phatt, *pprex, *pouts, *pW2T, *pWc;
    cudaGetSymbolAddress((void**)&ph,    g_h);
    cudaGetSymbolAddress((void**)&pqkv,  g_qkv);
    cudaGetSymbolAddress((void**)&pctx,  g_ctx);
    cudaGetSymbolAddress((void**)&ptmp,  g_tmp);
    cudaGetSymbolAddress((void**)&phatt, g_hatt);
    cudaGetSymbolAddress((void**)&pprex, g_prex);
    cudaGetSymbolAddress((void**)&pouts, g_outs);
    cudaGetSymbolAddress((void**)&pW2T,  g_W2T);
    cudaGetSymbolAddress((void**)&pWc,   g_Wc);

    cudaFuncSetAttribute(scan_kernel, cudaFuncAttributeMaxDynamicSharedMemorySize, SCAN_SMEM);

    init_kernel<<<1, 128>>>();

    // h = x @ in_proj_w^T + b
    gemm_tn<<<dim3(8, 128), 256>>>(x, 512, ipw, 512, ipb, ph, 8192, 512, 512);
    // qkv = h @ qkv_w^T + b
    gemm_tn<<<dim3(24, 128), 256>>>(ph, 512, qkvw, 512, qkvb, pqkv, 8192, 1536, 512);
    // attention
    attn_kernel<<<dim3(16, 64), 128>>>(pqkv, pctx);
    // attn out proj
    gemm_tn<<<dim3(8, 128), 256>>>(pctx, 512, aow, 512, aob, ptmp, 8192, 512, 512);
    // h_att = LN(h + attn_out)
    ln_kernel<<<8192, 128>>>(ph, ptmp, n1g, n1b, phatt);
    // prex = h_att @ W1x^T + b1  (x-half of ltc_w1, ldw = 1024)
    gemm_tn<<<dim3(8, 128), 256>>>(phatt, 512, w1, 1024, b1, pprex, 8192, 512, 512);
    // W2T, then Wc = [tw;gw;hw] @ W2   (as A @ (W2^T)^T)
    transpose_kernel<<<dim3(16, 16), dim3(32, 8)>>>(w2, pW2T);
    gemm_tn<<<dim3(8, 8), 256>>>(tw, 512, pW2T, 512, nullptr, pWc,            512, 512, 512);
    gemm_tn<<<dim3(8, 8), 256>>>(gw, 512, pW2T, 512, nullptr, pWc + 262144,   512, 512, 512);
    gemm_tn<<<dim3(8, 8), 256>>>(hw, 512, pW2T, 512, nullptr, pWc + 524288,   512, 512, 512);
    bc_kernel<<<6, 256>>>(tw, gw, hw, tb, gb, hb, b2);
    // persistent scan (4 independent 32-CTA groups)
    scan_kernel<<<NBLK, 128, SCAN_SMEM>>>(w1);
    // LN2 + out proj
    ln_kernel<<<8192, 128>>>(pouts, phatt, n2g, n2b, ptmp);
    gemm_tn<<<dim3(8, 128), 256>>>(ptmp, 512, ow, 512, ob, out, 8192, 512, 512);
}